// round 1
// baseline (speedup 1.0000x reference)
#include <cuda_runtime.h>

#define DIM 16

// Batch-independent precomputed constants (written by setup kernel each launch).
__device__ float2 g_P[3][4][4];     // [layer][qubit][2x2 elems 00,01,10,11]
__device__ float2 g_psi0[DIM];      // CZ * T0 |0>

__device__ __forceinline__ float2 cmul(float2 a, float2 b){
    return make_float2(fmaf(a.x, b.x, -a.y * b.y),
                       fmaf(a.x, b.y,  a.y * b.x));
}
__device__ __forceinline__ float2 cmadd(float2 a, float2 b, float2 acc){
    acc.x = fmaf(a.x, b.x, fmaf(-a.y, b.y, acc.x));
    acc.y = fmaf(a.x, b.y, fmaf( a.y, b.x, acc.y));
    return acc;
}
__device__ __forceinline__ void mm2(const float2* A, const float2* B, float2* C){
    C[0] = cmadd(A[1], B[2], cmul(A[0], B[0]));
    C[1] = cmadd(A[1], B[3], cmul(A[0], B[1]));
    C[2] = cmadd(A[3], B[2], cmul(A[2], B[0]));
    C[3] = cmadd(A[3], B[3], cmul(A[2], B[1]));
}

// One warp: build T[l][i] = Rz*Ry*Rx(theta), fold into P matrices and psi_init.
__global__ void vqc_setup(const float* __restrict__ theta){
    __shared__ float2 T[4][4][4];
    int t = threadIdx.x;
    if (t < 16){
        int l = t >> 2, i = t & 3;
        float t0 = theta[(l*4+i)*3 + 0];
        float t1 = theta[(l*4+i)*3 + 1];
        float t2 = theta[(l*4+i)*3 + 2];
        float cx, sx, cy, sy, cz, sz;
        sincosf(0.5f*t0, &sx, &cx);
        sincosf(0.5f*t1, &sy, &cy);
        sincosf(0.5f*t2, &sz, &cz);
        float2 RX[4] = {{cx,0.f},{0.f,-sx},{0.f,-sx},{cx,0.f}};
        float2 RY[4] = {{cy,0.f},{-sy,0.f},{sy,0.f},{cy,0.f}};
        float2 RZ[4] = {{cz,-sz},{0.f,0.f},{0.f,0.f},{cz,sz}};
        float2 YX[4], M[4];
        mm2(RY, RX, YX);
        mm2(RZ, YX, M);
        #pragma unroll
        for (int e = 0; e < 4; e++) T[l][i][e] = M[e];
    }
    __syncthreads();
    if (t < 12){
        int l = t >> 2, i = t & 3;
        float2 G[4];
        if (l < 2) mm2(T[l+1][i], T[3][i], G);
        else { G[0]=T[3][i][0]; G[1]=T[3][i][1]; G[2]=T[3][i][2]; G[3]=T[3][i][3]; }
        #pragma unroll
        for (int e = 0; e < 4; e++) g_P[l][i][e] = G[e];
    }
    if (t < 16){
        int s = t;
        float2 v = make_float2(1.f, 0.f);
        #pragma unroll
        for (int i = 0; i < 4; i++){
            int bi = (s >> (3 - i)) & 1;
            v = cmul(v, T[0][i][bi*2 + 0]);   // column 0 of T0_i
        }
        int b0=(s>>3)&1, b1=(s>>2)&1, b2=(s>>1)&1, b3=s&1;
        int e = (b0&b1) ^ (b1&b2) ^ (b2&b3) ^ (b0&b3);
        if (e) { v.x = -v.x; v.y = -v.y; }
        g_psi0[s] = v;
    }
}

__global__ void __launch_bounds__(256) vqc_main(
    const float4* __restrict__ x, const float* __restrict__ lmbd,
    float4* __restrict__ out, int B)
{
    __shared__ float2 sP[3][4][4];
    __shared__ float2 sPsi0[DIM];
    __shared__ float  sL[12];
    int t = threadIdx.x;
    if (t < 48) ((float2*)sP)[t] = ((const float2*)g_P)[t];
    if (t < DIM) sPsi0[t] = g_psi0[t];
    if (t < 12) sL[t] = lmbd[t];
    __syncthreads();

    int b = blockIdx.x * blockDim.x + t;
    if (b >= B) return;

    float4 xv = x[b];
    float xq[4] = {xv.x, xv.y, xv.z, xv.w};

    float2 r[DIM];
    #pragma unroll
    for (int s = 0; s < DIM; s++) r[s] = sPsi0[s];

    #pragma unroll
    for (int l = 0; l < 3; l++){
        float ch[4], sh[4];
        #pragma unroll
        for (int i = 0; i < 4; i++){
            float a = sL[l*4 + i] * xq[i];
            __sincosf(0.5f * a, &sh[i], &ch[i]);
        }
        #pragma unroll
        for (int i = 0; i < 4; i++){
            // z-angle shares trig with a0 (qubits 0,1) / a1 (qubits 2,3)
            float cz = (i < 2) ? ch[0] : ch[1];
            float sz = (i < 2) ? sh[0] : sh[1];
            float ci = ch[i], si = sh[i];
            float c2 = ci*ci, s2 = si*si, sc = si*ci;
            // M = Rz(z)*Ry(a)*Rx(a), SU(2): only top row needed explicitly
            float2 M00 = make_float2(fmaf(cz, c2,  sz*s2), fmaf(cz, s2, -sz*c2));
            float2 M01 = make_float2(-sc*(cz + sz), sc*(sz - cz));
            float2 M10 = make_float2(-M01.x,  M01.y);   // -conj(M01)
            float2 M11 = make_float2( M00.x, -M00.y);   //  conj(M00)
            // G = P * M (SU(2) * SU(2) -> SU(2); compute top row, derive bottom)
            float2 P00 = sP[l][i][0], P01 = sP[l][i][1];
            float2 G00 = cmadd(P01, M10, cmul(P00, M00));
            float2 G01 = cmadd(P01, M11, cmul(P00, M01));
            float2 G10 = make_float2(-G01.x,  G01.y);
            float2 G11 = make_float2( G00.x, -G00.y);
            // apply on qubit i (stride 8>>i)
            const int st = 8 >> i;
            #pragma unroll
            for (int j = 0; j < DIM; j++){
                if (j & st) continue;
                float2 p0 = r[j], p1 = r[j + st];
                r[j]      = cmadd(G01, p1, cmul(G00, p0));
                r[j + st] = cmadd(G11, p1, cmul(G10, p0));
            }
        }
        if (l < 2){   // CZ diag: -1 at states 3, 6, 9, 12
            r[3].x  = -r[3].x;  r[3].y  = -r[3].y;
            r[6].x  = -r[6].x;  r[6].y  = -r[6].y;
            r[9].x  = -r[9].x;  r[9].y  = -r[9].y;
            r[12].x = -r[12].x; r[12].y = -r[12].y;
        }
    }

    float o0=0.f, o1=0.f, o2=0.f, o3=0.f;
    #pragma unroll
    for (int s = 0; s < DIM; s++){
        float ps = fmaf(r[s].x, r[s].x, r[s].y * r[s].y);
        o0 += (s & 8) ? -ps : ps;
        o1 += (s & 4) ? -ps : ps;
        o2 += (s & 2) ? -ps : ps;
        o3 += (s & 1) ? -ps : ps;
    }
    out[b] = make_float4(o0, o1, o2, o3);
}

extern "C" void kernel_launch(void* const* d_in, const int* in_sizes, int n_in,
                              void* d_out, int out_size)
{
    const float* x     = (const float*)d_in[0];
    const float* theta = (const float*)d_in[1];
    const float* lmbd  = (const float*)d_in[2];
    int B = in_sizes[0] / 4;

    vqc_setup<<<1, 32>>>(theta);
    vqc_main<<<(B + 255) / 256, 256>>>((const float4*)x, lmbd, (float4*)d_out, B);
}

// round 2
// speedup vs baseline: 1.1077x; 1.1077x over previous
#include <cuda_runtime.h>
#include <cstdint>

#define DIM 16
typedef unsigned long long ull;

// Batch-independent precomputed constants (written by setup kernel each launch).
__device__ float2 g_P[3][4][4];     // [layer][qubit][2x2 elems 00,01,10,11]
__device__ float2 g_psi0[DIM];      // CZ * T0 |0>

// ---------- packed f32x2 helpers ----------
__device__ __forceinline__ ull pk(float lo, float hi){
    ull r;
    asm("mov.b64 %0, {%1, %2};" : "=l"(r) : "f"(lo), "f"(hi));
    return r;
}
__device__ __forceinline__ ull fma2(ull a, ull b, ull c){
    ull d;
    asm("fma.rn.f32x2 %0, %1, %2, %3;" : "=l"(d) : "l"(a), "l"(b), "l"(c));
    return d;
}
__device__ __forceinline__ ull mul2(ull a, ull b){
    ull d;
    asm("mul.rn.f32x2 %0, %1, %2;" : "=l"(d) : "l"(a), "l"(b));
    return d;
}
__device__ __forceinline__ ull swp(ull v){
    unsigned lo, hi;
    asm("mov.b64 {%0, %1}, %2;" : "=r"(lo), "=r"(hi) : "l"(v));
    ull r;
    asm("mov.b64 %0, {%1, %2};" : "=l"(r) : "r"(hi), "r"(lo));
    return r;
}
__device__ __forceinline__ void unpk(ull v, float& lo, float& hi){
    asm("mov.b64 {%0, %1}, %2;" : "=f"(lo), "=f"(hi) : "l"(v));
}

// ---------- scalar complex helpers (setup + G build) ----------
__device__ __forceinline__ float2 cmul(float2 a, float2 b){
    return make_float2(fmaf(a.x, b.x, -a.y * b.y),
                       fmaf(a.x, b.y,  a.y * b.x));
}
__device__ __forceinline__ float2 cmadd(float2 a, float2 b, float2 acc){
    acc.x = fmaf(a.x, b.x, fmaf(-a.y, b.y, acc.x));
    acc.y = fmaf(a.x, b.y, fmaf( a.y, b.x, acc.y));
    return acc;
}
__device__ __forceinline__ void mm2(const float2* A, const float2* B, float2* C){
    C[0] = cmadd(A[1], B[2], cmul(A[0], B[0]));
    C[1] = cmadd(A[1], B[3], cmul(A[0], B[1]));
    C[2] = cmadd(A[3], B[2], cmul(A[2], B[0]));
    C[3] = cmadd(A[3], B[3], cmul(A[2], B[1]));
}

// One warp: build T[l][i] = Rz*Ry*Rx(theta), fold into P matrices and psi_init.
__global__ void vqc_setup(const float* __restrict__ theta){
    __shared__ float2 T[4][4][4];
    int t = threadIdx.x;
    if (t < 16){
        int l = t >> 2, i = t & 3;
        float t0 = theta[(l*4+i)*3 + 0];
        float t1 = theta[(l*4+i)*3 + 1];
        float t2 = theta[(l*4+i)*3 + 2];
        float cx, sx, cy, sy, cz, sz;
        sincosf(0.5f*t0, &sx, &cx);
        sincosf(0.5f*t1, &sy, &cy);
        sincosf(0.5f*t2, &sz, &cz);
        float2 RX[4] = {{cx,0.f},{0.f,-sx},{0.f,-sx},{cx,0.f}};
        float2 RY[4] = {{cy,0.f},{-sy,0.f},{sy,0.f},{cy,0.f}};
        float2 RZ[4] = {{cz,-sz},{0.f,0.f},{0.f,0.f},{cz,sz}};
        float2 YX[4], M[4];
        mm2(RY, RX, YX);
        mm2(RZ, YX, M);
        #pragma unroll
        for (int e = 0; e < 4; e++) T[l][i][e] = M[e];
    }
    __syncthreads();
    if (t < 12){
        int l = t >> 2, i = t & 3;
        float2 G[4];
        if (l < 2) mm2(T[l+1][i], T[3][i], G);
        else { G[0]=T[3][i][0]; G[1]=T[3][i][1]; G[2]=T[3][i][2]; G[3]=T[3][i][3]; }
        #pragma unroll
        for (int e = 0; e < 4; e++) g_P[l][i][e] = G[e];
    }
    if (t < 16){
        int s = t;
        float2 v = make_float2(1.f, 0.f);
        #pragma unroll
        for (int i = 0; i < 4; i++){
            int bi = (s >> (3 - i)) & 1;
            v = cmul(v, T[0][i][bi*2 + 0]);   // column 0 of T0_i
        }
        int b0=(s>>3)&1, b1=(s>>2)&1, b2=(s>>1)&1, b3=s&1;
        int e = (b0&b1) ^ (b1&b2) ^ (b2&b3) ^ (b0&b3);
        if (e) { v.x = -v.x; v.y = -v.y; }
        g_psi0[s] = v;
    }
}

__global__ void __launch_bounds__(256) vqc_main(
    const float4* __restrict__ x, const float* __restrict__ lmbd,
    float4* __restrict__ out, int B)
{
    __shared__ float2 sP[3][4][4];
    __shared__ ull   sPsi0[DIM];
    __shared__ float sL[12];
    int t = threadIdx.x;
    if (t < 48) ((float2*)sP)[t] = ((const float2*)g_P)[t];
    if (t < DIM){
        float2 v = g_psi0[t];
        sPsi0[t] = pk(v.x, v.y);
    }
    if (t < 12) sL[t] = lmbd[t];
    __syncthreads();

    int b = blockIdx.x * blockDim.x + t;
    if (b >= B) return;

    float4 xv = x[b];
    float xq[4] = {xv.x, xv.y, xv.z, xv.w};

    ull r[DIM];
    #pragma unroll
    for (int s = 0; s < DIM; s++) r[s] = sPsi0[s];

    #pragma unroll
    for (int l = 0; l < 3; l++){
        float ch[4], sh[4];
        #pragma unroll
        for (int i = 0; i < 4; i++){
            float a = sL[l*4 + i] * xq[i];
            __sincosf(0.5f * a, &sh[i], &ch[i]);
        }
        #pragma unroll
        for (int i = 0; i < 4; i++){
            // z-angle shares trig with a0 (qubits 0,1) / a1 (qubits 2,3)
            float cz = (i < 2) ? ch[0] : ch[1];
            float sz = (i < 2) ? sh[0] : sh[1];
            float ci = ch[i], si = sh[i];
            float c2 = ci*ci, s2 = si*si, sc = si*ci;
            // M = Rz(z)*Ry(a)*Rx(a), SU(2): top row
            float2 M00 = make_float2(fmaf(cz, c2,  sz*s2), fmaf(cz, s2, -sz*c2));
            float2 M01 = make_float2(-sc*(cz + sz), sc*(sz - cz));
            float2 M10 = make_float2(-M01.x,  M01.y);   // -conj(M01)
            float2 M11 = make_float2( M00.x, -M00.y);   //  conj(M00)
            // G = P * M (SU(2): top row only)
            float2 P00 = sP[l][i][0], P01 = sP[l][i][1];
            float2 G00 = cmadd(P01, M10, cmul(P00, M00));
            float2 G01 = cmadd(P01, M11, cmul(P00, M01));
            // packed coefficient forms (6 distinct; G11/G10 reuse via SU(2))
            ull A1_00 = pk( G00.x,  G00.x);
            ull A2_00 = pk(-G00.y,  G00.y);
            ull A1_01 = pk( G01.x,  G01.x);
            ull A2_01 = pk(-G01.y,  G01.y);   // == A2_10
            ull A1_10 = pk(-G01.x, -G01.x);
            ull A2_11 = pk( G00.y, -G00.y);
            // apply on qubit i (stride 8>>i), packed complex arithmetic
            const int st = 8 >> i;
            #pragma unroll
            for (int j = 0; j < DIM; j++){
                if (j & st) continue;
                ull P0 = r[j], P1 = r[j + st];
                ull P0s = swp(P0), P1s = swp(P1);
                // row0 = G00*p0 + G01*p1
                ull t0 = fma2(A2_01, P1s, mul2(A1_01, P1));
                t0     = fma2(A2_00, P0s, t0);
                r[j]   = fma2(A1_00, P0, t0);
                // row1 = G10*p0 + G11*p1   (G10: A1_10, A2_01; G11: A1_00, A2_11)
                ull t1    = fma2(A2_01, P0s, mul2(A1_10, P0));
                t1        = fma2(A2_11, P1s, t1);
                r[j + st] = fma2(A1_00, P1, t1);
            }
        }
        if (l < 2){   // CZ diag: -1 at states 3, 6, 9, 12 (flip both sign bits)
            const ull SGN = 0x8000000080000000ull;
            r[3] ^= SGN; r[6] ^= SGN; r[9] ^= SGN; r[12] ^= SGN;
        }
    }

    // probs + Walsh-tree reduction to 4 <Z_q> values
    float ps[DIM];
    #pragma unroll
    for (int s = 0; s < DIM; s++){
        ull q = mul2(r[s], r[s]);
        float ql, qh; unpk(q, ql, qh);
        ps[s] = ql + qh;
    }
    float e[8], d3;
    d3 = (ps[0]-ps[1]) + (ps[2]-ps[3]) + (ps[4]-ps[5]) + (ps[6]-ps[7])
       + (ps[8]-ps[9]) + (ps[10]-ps[11]) + (ps[12]-ps[13]) + (ps[14]-ps[15]);
    #pragma unroll
    for (int k = 0; k < 8; k++) e[k] = ps[2*k] + ps[2*k+1];
    float f[4], d2;
    d2 = (e[0]-e[1]) + (e[2]-e[3]) + (e[4]-e[5]) + (e[6]-e[7]);
    #pragma unroll
    for (int k = 0; k < 4; k++) f[k] = e[2*k] + e[2*k+1];
    float g0 = f[0] + f[1], g1 = f[2] + f[3];
    float d1 = (f[0]-f[1]) + (f[2]-f[3]);
    float o0 = g0 - g1;

    out[b] = make_float4(o0, d1, d2, d3);
}

extern "C" void kernel_launch(void* const* d_in, const int* in_sizes, int n_in,
                              void* d_out, int out_size)
{
    const float* x     = (const float*)d_in[0];
    const float* theta = (const float*)d_in[1];
    const float* lmbd  = (const float*)d_in[2];
    int B = in_sizes[0] / 4;

    vqc_setup<<<1, 32>>>(theta);
    vqc_main<<<(B + 255) / 256, 256>>>((const float4*)x, lmbd, (float4*)d_out, B);
}